// round 6
// baseline (speedup 1.0000x reference)
#include <cuda_runtime.h>
#include <cstdint>

#define NA    57600     // 64*100*9 anchors
#define NLOC  6400      // 64*100
#define FW    100
#define PRE   6000
#define POST  300
#define NW    94        // ceil(6000/64) u64 words
#define CAP   8192
#define NBIN  65536
#define FULL  0xFFFFFFFFu
#define LOOK  8
#define NB    148       // one block per SM, wave-1 resident
#define NT    256
#define GSZ   (NB*NT)

typedef unsigned long long u64;

// Base anchors (ratios 0.5,1,2 x scales 8,16,32), numpy banker's rounding baked in.
__constant__ float c_base[36] = {
  -84.f,  -40.f,  99.f,  55.f,
 -176.f,  -88.f, 191.f, 103.f,
 -360.f, -184.f, 375.f, 199.f,
  -56.f,  -56.f,  71.f,  71.f,
 -120.f, -120.f, 135.f, 135.f,
 -248.f, -248.f, 263.f, 263.f,
  -36.f,  -80.f,  51.f,  95.f,
  -80.f, -168.f,  95.f, 183.f,
 -168.f, -344.f, 183.f, 359.f
};

__device__ float4   g_boxes[NA];
__device__ unsigned g_keys[NA];
__device__ unsigned g_hist[NBIN];
__device__ int      g_cnt;
__device__ unsigned g_B;
__device__ u64      g_cand[CAP];
__device__ float4   g_top[PRE];
__device__ u64      g_mask[(size_t)PRE * NW];
__device__ unsigned g_bar[8];     // barrier counters (reset at kernel end)
__device__ unsigned g_exit;

__device__ __forceinline__ void gbar(int i) {
    __syncthreads();
    if (threadIdx.x == 0) {
        __threadfence();
        unsigned arrived = atomicAdd(&g_bar[i], 1u) + 1u;
        if (arrived < NB)
            while (atomicAdd(&g_bar[i], 0u) < NB) { }
    }
    __syncthreads();
}

__global__ __launch_bounds__(NT) void k_all(const float* __restrict__ cls,
                                            const float* __restrict__ bbox,
                                            const int*   __restrict__ ihp,
                                            const int*   __restrict__ iwp,
                                            float*       __restrict__ out) {
    int tid  = threadIdx.x;
    int bid  = blockIdx.x;
    int gtid = bid * NT + tid;

    __shared__ u64      s_tile[NT];
    __shared__ float4   s_box[64];
    __shared__ int      s_keep[POST];
    __shared__ unsigned s_ws[8], s_wsuf[8];

    // ---------------- phase 0: zero hist + counter ----------------
    for (int i = gtid; i < NBIN; i += GSZ) g_hist[i] = 0u;
    if (gtid == 0) g_cnt = 0;
    gbar(0);

    // ---------------- phase 1: decode + 16-bit histogram ----------
    {
        float W = (float)(iwp[0] - 1);
        float H = (float)(ihp[0] - 1);
        for (int t = gtid; t < NA; t += GSZ) {
            int a = t / NLOC, loc = t % NLOC;
            int y = loc / FW, x = loc % FW;
            int ai = loc * 9 + a;

            float s0 = cls[(2 * a)     * NLOC + loc];
            float s1 = cls[(2 * a + 1) * NLOC + loc];
            float m  = fmaxf(s0, s1);
            float e0 = expf(s0 - m), e1 = expf(s1 - m);
            float score = e1 / (e0 + e1);

            float dx = bbox[(4 * a + 0) * NLOC + loc];
            float dy = bbox[(4 * a + 1) * NLOC + loc];
            float dw = bbox[(4 * a + 2) * NLOC + loc];
            float dh = bbox[(4 * a + 3) * NLOC + loc];

            float sx = (float)(x * 16), sy = (float)(y * 16);
            float ax1 = sx + c_base[a * 4 + 0];
            float ay1 = sy + c_base[a * 4 + 1];
            float ax2 = sx + c_base[a * 4 + 2];
            float ay2 = sy + c_base[a * 4 + 3];

            float w  = ax2 - ax1 + 1.0f;
            float h  = ay2 - ay1 + 1.0f;
            float cx = ax1 + 0.5f * w;
            float cy = ay1 + 0.5f * h;

            float pcx = dx * w + cx;
            float pcy = dy * h + cy;
            float pw  = expf(dw) * w;
            float ph  = expf(dh) * h;

            float x1 = fminf(fmaxf(pcx - 0.5f * pw, 0.f), W);
            float y1 = fminf(fmaxf(pcy - 0.5f * ph, 0.f), H);
            float x2 = fminf(fmaxf(pcx + 0.5f * pw, 0.f), W);
            float y2 = fminf(fmaxf(pcy + 0.5f * ph, 0.f), H);

            bool valid = (x2 - x1 + 1.f >= 16.f) && (y2 - y1 + 1.f >= 16.f);
            float s = valid ? score : -1e30f;

            unsigned u = __float_as_uint(s);
            unsigned key = (u & 0x80000000u) ? ~u : (u | 0x80000000u);

            g_keys[t]   = key;
            g_boxes[ai] = make_float4(x1, y1, x2, y2);
            atomicAdd(&g_hist[key >> 16], 1u);
        }
    }
    gbar(1);

    // ---------------- phase 2: threshold bin (block 0) ------------
    if (bid == 0) {
        int lane = tid & 31, warp = tid >> 5;
        const uint4* h4 = (const uint4*)(g_hist) + tid * 64;   // 256 bins/thread
        unsigned c = 0;
        #pragma unroll 16
        for (int q = 0; q < 64; q++) {
            uint4 v = h4[q];
            c += v.x + v.y + v.z + v.w;
        }
        unsigned suf = c;
        #pragma unroll
        for (int off = 1; off < 32; off <<= 1) {
            unsigned v = __shfl_down_sync(FULL, suf, off);
            if (lane + off < 32) suf += v;
        }
        if (lane == 0) s_ws[warp] = suf;
        __syncthreads();
        if (warp == 0 && lane < 8) {
            unsigned ws = s_ws[lane];
            unsigned s2 = ws;
            #pragma unroll
            for (int off = 1; off < 8; off <<= 1) {
                unsigned v = __shfl_down_sync(0xFFu, s2, off);
                if (lane + off < 8) s2 += v;
            }
            s_wsuf[lane] = s2 - ws;
        }
        __syncthreads();
        unsigned suffInc = suf + s_wsuf[warp];
        unsigned above   = suffInc - c;
        if (above < PRE && suffInc >= PRE) {
            unsigned run = above;
            int base = tid * 256;
            for (int b = 255; b >= 0; b--) {
                run += g_hist[base + b];
                if (run >= PRE) { g_B = (unsigned)(base + b); break; }
            }
        }
    }
    gbar(2);

    // ---------------- phase 3: compact candidates -----------------
    {
        unsigned B = g_B;
        for (int t = gtid; t < NA; t += GSZ) {
            unsigned key = g_keys[t];
            if ((key >> 16) >= B) {
                int p = atomicAdd(&g_cnt, 1);
                if (p < CAP) {
                    int a = t / NLOC, loc = t % NLOC;
                    unsigned ai = (unsigned)(loc * 9 + a);
                    g_cand[p] = ((u64)key << 32) | (~ai);
                }
            }
        }
    }
    gbar(3);

    // ---------------- phase 4: exact rank (blocks 0..31) ----------
    if (bid < CAP / NT) {
        int cnt = g_cnt; if (cnt > CAP) cnt = CAP;
        int p = bid * NT + tid;
        u64 v = (p < cnt) ? g_cand[p] : 0ULL;
        int rank = 0;
        for (int t0 = 0; t0 < cnt; t0 += NT) {
            int j = t0 + tid;
            s_tile[tid] = (j < cnt) ? g_cand[j] : 0ULL;
            __syncthreads();
            int lim = min(NT, cnt - t0);
            #pragma unroll 4
            for (int q = 0; q < lim; q++) rank += (s_tile[q] > v);
            __syncthreads();
        }
        if (p < cnt && rank < PRE) {
            unsigned idx = ~(unsigned)v;
            g_top[rank] = g_boxes[idx];
        }
    }
    gbar(4);

    // ---------------- phase 5: IoU bitmask (256-row tiles) --------
    {
        const int RT = (PRE + NT - 1) / NT;     // 24 row tiles
        for (int tile = bid; tile < RT * NW; tile += NB) {
            int rt = tile / NW, cb = tile - rt * NW;
            int i = rt * NT + tid;
            if (cb * 64 + 63 < rt * NT) {       // whole tile below diagonal
                if (i < PRE) g_mask[(size_t)i * NW + cb] = 0ULL;
                continue;                        // uniform per block
            }
            int j0 = cb * 64;
            if (tid < 64) {
                int jg = j0 + tid;
                s_box[tid] = (jg < PRE) ? g_top[jg] : make_float4(0.f, 0.f, 0.f, 0.f);
            }
            __syncthreads();
            if (i < PRE) {
                float4 bi = g_top[i];
                float ai = (bi.z - bi.x) * (bi.w - bi.y);
                u64 bits = 0ULL;
                #pragma unroll 4
                for (int b = 0; b < 64; b++) {
                    int j = j0 + b;
                    float4 bj = s_box[b];
                    float aj = (bj.z - bj.x) * (bj.w - bj.y);
                    float lx = fmaxf(bi.x, bj.x), ly = fmaxf(bi.y, bj.y);
                    float rx = fminf(bi.z, bj.z), ry = fminf(bi.w, bj.w);
                    float ww = fmaxf(rx - lx, 0.f), hh = fmaxf(ry - ly, 0.f);
                    float inter = ww * hh;
                    float iou = inter / (ai + aj - inter);
                    if (j > i && j < PRE && iou > 0.7f) bits |= 1ULL << b;
                }
                g_mask[(size_t)i * NW + cb] = bits;
            }
            __syncthreads();
        }
    }
    gbar(5);

    // ---------------- phase 6: serial NMS (block 0 warp 0) + exit --
    if (bid == 0) {
        if (tid < 32) {
            int lane = tid;
            u64 rem0 = 0ULL, rem1 = 0ULL, rem2 = 0ULL;
            if (lane == 29) rem2 = (~0ULL) << 48;
            if (lane >= 30) rem2 = ~0ULL;

            int nk = 0;
            while (nk < POST) {
                u64 f0 = ~rem0, f1 = ~rem1, f2 = ~rem2;
                unsigned b0 = __ballot_sync(FULL, f0 != 0ULL);
                unsigned b1 = __ballot_sync(FULL, f1 != 0ULL);
                unsigned b2 = __ballot_sync(FULL, f2 != 0ULL);
                int wsel; u64 wfree;
                if (b0) {
                    int src = __ffs(b0) - 1; wsel = src;
                    wfree = __shfl_sync(FULL, f0, src);
                } else if (b1) {
                    int src = __ffs(b1) - 1; wsel = src + 32;
                    wfree = __shfl_sync(FULL, f1, src);
                } else if (b2) {
                    int src = __ffs(b2) - 1; wsel = src + 64;
                    wfree = __shfl_sync(FULL, f2, src);
                } else break;

                int j[LOOK];
                u64 tbits = wfree;
                #pragma unroll
                for (int m = 0; m < LOOK; m++) {
                    if (tbits) {
                        int b = __ffsll((long long)tbits) - 1;
                        j[m] = (wsel << 6) + b;
                        tbits &= tbits - 1;
                    } else j[m] = PRE;
                }

                u64 r0[LOOK], r1[LOOK], r2[LOOK];
                #pragma unroll
                for (int m = 0; m < LOOK; m++) {
                    if (j[m] < PRE) {
                        const u64* row = g_mask + (size_t)j[m] * NW;
                        r0[m] = row[lane];
                        r1[m] = row[lane + 32];
                        r2[m] = (lane + 64 < NW) ? row[lane + 64] : 0ULL;
                    } else { r0[m] = 0ULL; r1[m] = 0ULL; r2[m] = 0ULL; }
                }

                #pragma unroll
                for (int m = 0; m < LOOK; m++) {
                    int jm = j[m];
                    if (jm >= PRE) break;
                    int w = jm >> 6;
                    u64 bit = 1ULL << (jm & 63);
                    bool own0 = (lane == w);
                    bool own1 = (lane == w - 32);
                    bool own2 = (lane == w - 64);
                    bool supp = (own0 && (rem0 & bit)) || (own1 && (rem1 & bit)) ||
                                (own2 && (rem2 & bit));
                    if (__any_sync(FULL, supp)) continue;
                    if (lane == 0) s_keep[nk] = jm;
                    nk++;
                    rem0 |= r0[m]; rem1 |= r1[m]; rem2 |= r2[m];
                    if (own0) rem0 |= bit;
                    if (own1) rem1 |= bit;
                    if (own2) rem2 |= bit;
                    if (nk == POST) break;
                }
            }

            __syncwarp();
            for (int k = nk + lane; k < POST; k += 32) s_keep[k] = 0;
            __syncwarp();
            for (int k = lane; k < POST; k += 32) {
                float4 b = g_top[s_keep[k]];
                out[k * 5 + 0] = 0.f;
                out[k * 5 + 1] = b.x;
                out[k * 5 + 2] = b.y;
                out[k * 5 + 3] = b.z;
                out[k * 5 + 4] = b.w;
            }
        }
        __syncthreads();
        if (tid == 0) {
            // wait for all other blocks to finish, then reset barrier state
            while (atomicAdd(&g_exit, 0u) < NB - 1) { }
            #pragma unroll
            for (int q = 0; q < 8; q++) g_bar[q] = 0u;
            g_exit = 0u;
            __threadfence();
        }
    } else {
        if (tid == 0) { __threadfence(); atomicAdd(&g_exit, 1u); }
    }
}

// ---------------------------------------------------------------- launch
extern "C" void kernel_launch(void* const* d_in, const int* in_sizes, int n_in,
                              void* d_out, int out_size) {
    const float* cls  = (const float*)d_in[0];
    const float* bbox = (const float*)d_in[1];
    const int*   ih   = (const int*)d_in[2];
    const int*   iw   = (const int*)d_in[3];
    float* out = (float*)d_out;

    k_all<<<NB, NT>>>(cls, bbox, ih, iw, out);
}

// round 7
// speedup vs baseline: 1.3814x; 1.3814x over previous
#include <cuda_runtime.h>
#include <cstdint>

#define NA    57600     // 64*100*9 anchors
#define NLOC  6400      // 64*100
#define FW    100
#define PRE   6000
#define POST  300
#define NW    94        // ceil(6000/64) u64 words
#define CAP   8192
#define NBIN  65536
#define FULL  0xFFFFFFFFu
#define LOOK  16

typedef unsigned long long u64;

// Base anchors (ratios 0.5,1,2 x scales 8,16,32), numpy banker's rounding baked in.
__constant__ float c_base[36] = {
  -84.f,  -40.f,  99.f,  55.f,
 -176.f,  -88.f, 191.f, 103.f,
 -360.f, -184.f, 375.f, 199.f,
  -56.f,  -56.f,  71.f,  71.f,
 -120.f, -120.f, 135.f, 135.f,
 -248.f, -248.f, 263.f, 263.f,
  -36.f,  -80.f,  51.f,  95.f,
  -80.f, -168.f,  95.f, 183.f,
 -168.f, -344.f, 183.f, 359.f
};

__device__ float4   g_boxes[NA];   // indexed by reference anchor id
__device__ unsigned g_keys[NA];    // (a,loc) layout, coalesced
__device__ unsigned g_hist[NBIN];
__device__ int      g_cnt;
__device__ unsigned g_B;           // 16-bit threshold bin
__device__ u64      g_cand[CAP];
__device__ float4   g_top[PRE];
__device__ u64      g_mask[(size_t)PRE * NW];   // triangular: words < i/64 of row i are NOT written

// ---------------------------------------------------------------- init
__global__ void k_init() {
    int i = blockIdx.x * blockDim.x + threadIdx.x;
    int stride = gridDim.x * blockDim.x;
    uint4 z = make_uint4(0u, 0u, 0u, 0u);
    uint4* h4 = (uint4*)g_hist;
    for (; i < NBIN / 4; i += stride) h4[i] = z;
    if (blockIdx.x == 0 && threadIdx.x == 0) g_cnt = 0;
}

// ---------------------------------------------------------------- decode + histogram
__global__ void k_decode(const float* __restrict__ cls,
                         const float* __restrict__ bbox,
                         const int*   __restrict__ ih,
                         const int*   __restrict__ iw) {
    int t = blockIdx.x * blockDim.x + threadIdx.x;
    if (t >= NA) return;
    int a = t / NLOC, loc = t % NLOC;       // coalesced channel reads
    int y = loc / FW, x = loc % FW;
    int ai = loc * 9 + a;                   // reference anchor index

    float s0 = cls[(2 * a)     * NLOC + loc];
    float s1 = cls[(2 * a + 1) * NLOC + loc];
    float m  = fmaxf(s0, s1);
    float e0 = expf(s0 - m), e1 = expf(s1 - m);
    float score = e1 / (e0 + e1);

    float dx = bbox[(4 * a + 0) * NLOC + loc];
    float dy = bbox[(4 * a + 1) * NLOC + loc];
    float dw = bbox[(4 * a + 2) * NLOC + loc];
    float dh = bbox[(4 * a + 3) * NLOC + loc];

    float sx = (float)(x * 16), sy = (float)(y * 16);
    float ax1 = sx + c_base[a * 4 + 0];
    float ay1 = sy + c_base[a * 4 + 1];
    float ax2 = sx + c_base[a * 4 + 2];
    float ay2 = sy + c_base[a * 4 + 3];

    float w  = ax2 - ax1 + 1.0f;
    float h  = ay2 - ay1 + 1.0f;
    float cx = ax1 + 0.5f * w;
    float cy = ay1 + 0.5f * h;

    float pcx = dx * w + cx;
    float pcy = dy * h + cy;
    float pw  = expf(dw) * w;
    float ph  = expf(dh) * h;

    float W = (float)(iw[0] - 1);
    float H = (float)(ih[0] - 1);
    float x1 = fminf(fmaxf(pcx - 0.5f * pw, 0.f), W);
    float y1 = fminf(fmaxf(pcy - 0.5f * ph, 0.f), H);
    float x2 = fminf(fmaxf(pcx + 0.5f * pw, 0.f), W);
    float y2 = fminf(fmaxf(pcy + 0.5f * ph, 0.f), H);

    bool valid = (x2 - x1 + 1.f >= 16.f) && (y2 - y1 + 1.f >= 16.f);
    float s = valid ? score : -1e30f;

    unsigned u = __float_as_uint(s);
    unsigned key = (u & 0x80000000u) ? ~u : (u | 0x80000000u);

    g_keys[t]   = key;
    g_boxes[ai] = make_float4(x1, y1, x2, y2);
    atomicAdd(&g_hist[key >> 16], 1u);
}

// ---------------------------------------------------------------- threshold bin (high 16 bits), vectorized + shfl scan
__global__ void k_thresh() {
    __shared__ unsigned warpsum[32];
    __shared__ unsigned warpsuf[32];
    int t = threadIdx.x;            // 1024 threads
    int lane = t & 31, warp = t >> 5;

    const uint4* h4 = (const uint4*)(g_hist) + t * 16;
    unsigned c = 0;
    #pragma unroll
    for (int q = 0; q < 16; q++) {
        uint4 v = h4[q];
        c += v.x + v.y + v.z + v.w;
    }

    unsigned suf = c;
    #pragma unroll
    for (int off = 1; off < 32; off <<= 1) {
        unsigned v = __shfl_down_sync(FULL, suf, off);
        if (lane + off < 32) suf += v;
    }
    if (lane == 0) warpsum[warp] = suf;
    __syncthreads();
    if (warp == 0) {
        unsigned ws = warpsum[lane];
        unsigned s2 = ws;
        #pragma unroll
        for (int off = 1; off < 32; off <<= 1) {
            unsigned v = __shfl_down_sync(FULL, s2, off);
            if (lane + off < 32) s2 += v;
        }
        warpsuf[lane] = s2 - ws;
    }
    __syncthreads();

    unsigned suffInc = suf + warpsuf[warp];
    unsigned above   = suffInc - c;
    if (above < PRE && suffInc >= PRE) {
        unsigned run = above;
        int base = t * 64;
        for (int b = 63; b >= 0; b--) {
            run += g_hist[base + b];
            if (run >= PRE) { g_B = (unsigned)(base + b); break; }
        }
    }
}

// ---------------------------------------------------------------- compact candidates (bin >= threshold bin)
__global__ void k_compact() {
    int t = blockIdx.x * blockDim.x + threadIdx.x;
    if (t >= NA) return;
    unsigned key = g_keys[t];
    if ((key >> 16) >= g_B) {
        int p = atomicAdd(&g_cnt, 1);
        if (p < CAP) {
            int a = t / NLOC, loc = t % NLOC;
            unsigned ai = (unsigned)(loc * 9 + a);
            g_cand[p] = ((u64)key << 32) | (~ai);
        }
    }
}

// ---------------------------------------------------------------- exact rank by all-pairs compare
__global__ void k_rank() {
    __shared__ u64 tile[256];
    int cnt = g_cnt; if (cnt > CAP) cnt = CAP;
    int p = blockIdx.x * blockDim.x + threadIdx.x;
    u64 v = (p < cnt) ? g_cand[p] : 0ULL;
    int rank = 0;
    for (int t0 = 0; t0 < cnt; t0 += 256) {
        int j = t0 + threadIdx.x;
        tile[threadIdx.x] = (j < cnt) ? g_cand[j] : 0ULL;
        __syncthreads();
        int lim = min(256, cnt - t0);
        #pragma unroll 4
        for (int q = 0; q < lim; q++) rank += (tile[q] > v);
        __syncthreads();
    }
    if (p < cnt && rank < PRE) {
        unsigned idx = ~(unsigned)v;
        g_top[rank] = g_boxes[idx];
    }
}

// ---------------------------------------------------------------- IoU bitmask matrix, upper-triangular only
__global__ void k_mask() {
    __shared__ float4 sb[64];
    int cb = blockIdx.x, rb = blockIdx.y, t = threadIdx.x;
    if (cb < rb) return;           // sub-diagonal: never written, never read
    int i = rb * 64 + t;
    int j0 = cb * 64;
    int jg = j0 + t;
    sb[t] = (jg < PRE) ? g_top[jg] : make_float4(0.f, 0.f, 0.f, 0.f);
    __syncthreads();
    if (i >= PRE) return;
    float4 bi = g_top[i];
    float ai = (bi.z - bi.x) * (bi.w - bi.y);
    u64 bits = 0ULL;
    #pragma unroll 4
    for (int b = 0; b < 64; b++) {
        int j = j0 + b;
        float4 bj = sb[b];
        float aj = (bj.z - bj.x) * (bj.w - bj.y);
        float lx = fmaxf(bi.x, bj.x), ly = fmaxf(bi.y, bj.y);
        float rx = fminf(bi.z, bj.z), ry = fminf(bi.w, bj.w);
        float ww = fmaxf(rx - lx, 0.f), hh = fmaxf(ry - ly, 0.f);
        float inter = ww * hh;
        float iou = inter / (ai + aj - inter);
        if (j > i && j < PRE && iou > 0.7f) bits |= 1ULL << b;
    }
    g_mask[(size_t)i * NW + cb] = bits;
}

// ---------------------------------------------------------------- serial NMS: 1 warp, regs bitmap, 16-wide / 2-word lookahead
__global__ void k_nms(float* __restrict__ out) {
    __shared__ int s_keep[POST];
    int lane = threadIdx.x;        // 32 threads

    // lane owns words: lane, lane+32, lane+64  (valid words < 94)
    u64 rem0 = 0ULL, rem1 = 0ULL, rem2 = 0ULL;
    if (lane == 29) rem2 = (~0ULL) << 48;    // word 93: indices 6000..6015 invalid
    if (lane >= 30) rem2 = ~0ULL;            // words 94,95 don't exist

    int nk = 0;
    while (nk < POST) {
        // ---- free-word ballots (once per round)
        u64 f0 = ~rem0, f1 = ~rem1, f2 = ~rem2;
        unsigned b0 = __ballot_sync(FULL, f0 != 0ULL);
        unsigned b1 = __ballot_sync(FULL, f1 != 0ULL);
        unsigned b2 = __ballot_sync(FULL, f2 != 0ULL);

        // ---- pick first free word
        int wsel1; u64 wfree1;
        if (b0) {
            int src = __ffs(b0) - 1; wsel1 = src;
            wfree1 = __shfl_sync(FULL, f0, src);
            b0 &= b0 - 1;
        } else if (b1) {
            int src = __ffs(b1) - 1; wsel1 = src + 32;
            wfree1 = __shfl_sync(FULL, f1, src);
            b1 &= b1 - 1;
        } else if (b2) {
            int src = __ffs(b2) - 1; wsel1 = src + 64;
            wfree1 = __shfl_sync(FULL, f2, src);
            b2 &= b2 - 1;
        } else break;

        // ---- pick second free word (no new ballots needed)
        int wsel2 = 0; u64 wfree2 = 0ULL;
        if (b0) {
            int src = __ffs(b0) - 1; wsel2 = src;
            wfree2 = __shfl_sync(FULL, f0, src);
        } else if (b1) {
            int src = __ffs(b1) - 1; wsel2 = src + 32;
            wfree2 = __shfl_sync(FULL, f1, src);
        } else if (b2) {
            int src = __ffs(b2) - 1; wsel2 = src + 64;
            wfree2 = __shfl_sync(FULL, f2, src);
        }

        // ---- extract up to LOOK lowest free indices across the two words
        int j[LOOK];
        u64 t1 = wfree1, t2 = wfree2;
        #pragma unroll
        for (int m = 0; m < LOOK; m++) {
            if (t1) {
                int b = __ffsll((long long)t1) - 1;
                j[m] = (wsel1 << 6) + b;
                t1 &= t1 - 1;
            } else if (t2) {
                int b = __ffsll((long long)t2) - 1;
                j[m] = (wsel2 << 6) + b;
                t2 &= t2 - 1;
            } else j[m] = PRE;
        }

        // ---- prefetch all candidate rows (triangular: clamp words < start)
        u64 r0[LOOK], r1[LOOK], r2[LOOK];
        #pragma unroll
        for (int m = 0; m < LOOK; m++) {
            if (j[m] < PRE) {
                int sw = j[m] >> 6;
                const u64* row = g_mask + (size_t)j[m] * NW;
                r0[m] = (lane      >= sw)                    ? row[lane]      : 0ULL;
                r1[m] = (lane + 32 >= sw)                    ? row[lane + 32] : 0ULL;
                r2[m] = (lane + 64 >= sw && lane + 64 < NW)  ? row[lane + 64] : 0ULL;
            } else { r0[m] = 0ULL; r1[m] = 0ULL; r2[m] = 0ULL; }
        }

        // ---- decide candidates in ascending order
        #pragma unroll
        for (int m = 0; m < LOOK; m++) {
            int jm = j[m];
            if (jm >= PRE) break;
            int w = jm >> 6;
            u64 bit = 1ULL << (jm & 63);
            bool own0 = (lane == w);
            bool own1 = (lane == w - 32);
            bool own2 = (lane == w - 64);
            bool supp = (own0 && (rem0 & bit)) || (own1 && (rem1 & bit)) ||
                        (own2 && (rem2 & bit));
            if (__any_sync(FULL, supp)) continue;   // suppressed
            if (lane == 0) s_keep[nk] = jm;
            nk++;
            rem0 |= r0[m]; rem1 |= r1[m]; rem2 |= r2[m];
            if (own0) rem0 |= bit;
            if (own1) rem1 |= bit;
            if (own2) rem2 |= bit;
            if (nk == POST) break;
        }
    }

    __syncwarp();
    for (int k = nk + lane; k < POST; k += 32) s_keep[k] = 0;
    __syncwarp();
    for (int k = lane; k < POST; k += 32) {
        float4 b = g_top[s_keep[k]];
        out[k * 5 + 0] = 0.f;
        out[k * 5 + 1] = b.x;
        out[k * 5 + 2] = b.y;
        out[k * 5 + 3] = b.z;
        out[k * 5 + 4] = b.w;
    }
}

// ---------------------------------------------------------------- launch
extern "C" void kernel_launch(void* const* d_in, const int* in_sizes, int n_in,
                              void* d_out, int out_size) {
    const float* cls  = (const float*)d_in[0];
    const float* bbox = (const float*)d_in[1];
    const int*   ih   = (const int*)d_in[2];
    const int*   iw   = (const int*)d_in[3];
    float* out = (float*)d_out;

    k_init   <<<64, 256>>>();
    k_decode <<<(NA + 255) / 256, 256>>>(cls, bbox, ih, iw);
    k_thresh <<<1, 1024>>>();
    k_compact<<<(NA + 255) / 256, 256>>>();
    k_rank   <<<CAP / 256, 256>>>();
    k_mask   <<<dim3(NW, NW), 64>>>();
    k_nms    <<<1, 32>>>(out);
}

// round 8
// speedup vs baseline: 1.7371x; 1.2575x over previous
#include <cuda_runtime.h>
#include <cstdint>

#define NA    57600     // 64*100*9 anchors
#define NLOC  6400      // 64*100
#define FW    100
#define PRE   6000
#define POST  300
#define NW    94        // ceil(6000/64) u64 words
#define CAP   8192
#define NBIN  65536
#define NCO   1024
#define FULL  0xFFFFFFFFu
#define LOOK  16

typedef unsigned long long u64;

// Base anchors (ratios 0.5,1,2 x scales 8,16,32), numpy banker's rounding baked in.
__constant__ float c_base[36] = {
  -84.f,  -40.f,  99.f,  55.f,
 -176.f,  -88.f, 191.f, 103.f,
 -360.f, -184.f, 375.f, 199.f,
  -56.f,  -56.f,  71.f,  71.f,
 -120.f, -120.f, 135.f, 135.f,
 -248.f, -248.f, 263.f, 263.f,
  -36.f,  -80.f,  51.f,  95.f,
  -80.f, -168.f,  95.f, 183.f,
 -168.f, -344.f, 183.f, 359.f
};

// NOTE: g_hist/g_coarse/g_rank/g_cnt must be ZERO on entry to each run.
// They start zero (static init) and are re-zeroed by k_mask each run.
__device__ float4   g_boxes[NA];
__device__ unsigned g_keys[NA];
__device__ unsigned g_hist[NBIN];
__device__ unsigned g_coarse[NCO];
__device__ int      g_cnt;
__device__ unsigned g_B;
__device__ u64      g_cand[CAP];
__device__ int      g_rank[CAP];
__device__ float4   g_top[PRE];
__device__ u64      g_mask[(size_t)PRE * NW];   // triangular: words < i/64 of row i NOT written

// ---------------------------------------------------------------- decode + fine/coarse histograms
__global__ void k_decode(const float* __restrict__ cls,
                         const float* __restrict__ bbox,
                         const int*   __restrict__ ih,
                         const int*   __restrict__ iw) {
    int t = blockIdx.x * blockDim.x + threadIdx.x;
    if (t >= NA) return;
    int a = t / NLOC, loc = t % NLOC;       // coalesced channel reads
    int y = loc / FW, x = loc % FW;
    int ai = loc * 9 + a;                   // reference anchor index

    float s0 = cls[(2 * a)     * NLOC + loc];
    float s1 = cls[(2 * a + 1) * NLOC + loc];
    float m  = fmaxf(s0, s1);
    float e0 = expf(s0 - m), e1 = expf(s1 - m);
    float score = e1 / (e0 + e1);

    float dx = bbox[(4 * a + 0) * NLOC + loc];
    float dy = bbox[(4 * a + 1) * NLOC + loc];
    float dw = bbox[(4 * a + 2) * NLOC + loc];
    float dh = bbox[(4 * a + 3) * NLOC + loc];

    float sx = (float)(x * 16), sy = (float)(y * 16);
    float ax1 = sx + c_base[a * 4 + 0];
    float ay1 = sy + c_base[a * 4 + 1];
    float ax2 = sx + c_base[a * 4 + 2];
    float ay2 = sy + c_base[a * 4 + 3];

    float w  = ax2 - ax1 + 1.0f;
    float h  = ay2 - ay1 + 1.0f;
    float cx = ax1 + 0.5f * w;
    float cy = ay1 + 0.5f * h;

    float pcx = dx * w + cx;
    float pcy = dy * h + cy;
    float pw  = expf(dw) * w;
    float ph  = expf(dh) * h;

    float W = (float)(iw[0] - 1);
    float H = (float)(ih[0] - 1);
    float x1 = fminf(fmaxf(pcx - 0.5f * pw, 0.f), W);
    float y1 = fminf(fmaxf(pcy - 0.5f * ph, 0.f), H);
    float x2 = fminf(fmaxf(pcx + 0.5f * pw, 0.f), W);
    float y2 = fminf(fmaxf(pcy + 0.5f * ph, 0.f), H);

    bool valid = (x2 - x1 + 1.f >= 16.f) && (y2 - y1 + 1.f >= 16.f);
    float s = valid ? score : -1e30f;

    unsigned u = __float_as_uint(s);
    unsigned key = (u & 0x80000000u) ? ~u : (u | 0x80000000u);

    g_keys[t]   = key;
    g_boxes[ai] = make_float4(x1, y1, x2, y2);
    atomicAdd(&g_hist[key >> 16], 1u);
    atomicAdd(&g_coarse[key >> 22], 1u);
}

// ---------------------------------------------------------------- threshold bin via coarse hist (1 block)
__global__ void k_thresh() {
    __shared__ unsigned warpsum[32];
    __shared__ unsigned warpsuf[32];
    int t = threadIdx.x;            // 1024 threads, one per coarse bucket
    int lane = t & 31, warp = t >> 5;

    unsigned c = g_coarse[t];

    unsigned suf = c;
    #pragma unroll
    for (int off = 1; off < 32; off <<= 1) {
        unsigned v = __shfl_down_sync(FULL, suf, off);
        if (lane + off < 32) suf += v;
    }
    if (lane == 0) warpsum[warp] = suf;
    __syncthreads();
    if (warp == 0) {
        unsigned ws = warpsum[lane];
        unsigned s2 = ws;
        #pragma unroll
        for (int off = 1; off < 32; off <<= 1) {
            unsigned v = __shfl_down_sync(FULL, s2, off);
            if (lane + off < 32) s2 += v;
        }
        warpsuf[lane] = s2 - ws;
    }
    __syncthreads();

    unsigned suffInc = suf + warpsuf[warp];
    unsigned above   = suffInc - c;
    if (above < PRE && suffInc >= PRE) {
        unsigned run = above;
        int base = t * 64;          // coarse bucket t = fine bins [t*64, t*64+64)
        for (int b = 63; b >= 0; b--) {
            run += g_hist[base + b];
            if (run >= PRE) { g_B = (unsigned)(base + b); break; }
        }
    }
}

// ---------------------------------------------------------------- compact candidates (bin >= threshold bin)
__global__ void k_compact() {
    int t = blockIdx.x * blockDim.x + threadIdx.x;
    if (t >= NA) return;
    unsigned key = g_keys[t];
    if ((key >> 16) >= g_B) {
        int p = atomicAdd(&g_cnt, 1);
        if (p < CAP) {
            int a = t / NLOC, loc = t % NLOC;
            unsigned ai = (unsigned)(loc * 9 + a);
            g_cand[p] = ((u64)key << 32) | (~ai);
        }
    }
}

// ---------------------------------------------------------------- 2D-parallel exact rank (partial counts via atomics)
__global__ void k_rank2d() {
    __shared__ u64 tile[256];
    int cnt = g_cnt; if (cnt > CAP) cnt = CAP;
    int t0 = blockIdx.y * 256;
    if (t0 >= cnt) return;
    int j = t0 + threadIdx.x;
    tile[threadIdx.x] = (j < cnt) ? g_cand[j] : 0ULL;   // zeros never beat valid keys
    __syncthreads();
    int p = blockIdx.x * 256 + threadIdx.x;
    if (p >= cnt) return;
    u64 v = g_cand[p];
    int r = 0;
    #pragma unroll 8
    for (int q = 0; q < 256; q++) r += (tile[q] > v);
    if (r) atomicAdd(&g_rank[p], r);
}

// ---------------------------------------------------------------- scatter boxes to rank order
__global__ void k_scatter() {
    int cnt = g_cnt; if (cnt > CAP) cnt = CAP;
    int p = blockIdx.x * 256 + threadIdx.x;
    if (p >= cnt) return;
    int r = g_rank[p];
    if (r < PRE) {
        u64 v = g_cand[p];
        unsigned idx = ~(unsigned)v;
        g_top[r] = g_boxes[idx];
    }
}

// ---------------------------------------------------------------- IoU bitmask (upper-triangular) + state re-zero
__global__ void k_mask() {
    __shared__ float4 sb[64];
    int cb = blockIdx.x, rb = blockIdx.y, t = threadIdx.x;

    // housekeeping for the NEXT run: zero hist/coarse/rank/cnt (safe: all
    // consumers of these ran in earlier kernels of THIS run)
    {
        int bid = blockIdx.y * gridDim.x + blockIdx.x;
        int gt  = bid * 64 + t;
        if (gt < NBIN)                       g_hist[gt] = 0u;
        else if (gt < NBIN + NCO)            g_coarse[gt - NBIN] = 0u;
        else if (gt < NBIN + NCO + CAP)      g_rank[gt - NBIN - NCO] = 0;
        else if (gt == NBIN + NCO + CAP)     g_cnt = 0;
    }

    if (cb < rb) return;           // sub-diagonal: never written, never read
    int i = rb * 64 + t;
    int j0 = cb * 64;
    int jg = j0 + t;
    sb[t] = (jg < PRE) ? g_top[jg] : make_float4(0.f, 0.f, 0.f, 0.f);
    __syncthreads();
    if (i >= PRE) return;
    float4 bi = g_top[i];
    float ai = (bi.z - bi.x) * (bi.w - bi.y);
    u64 bits = 0ULL;
    #pragma unroll 4
    for (int b = 0; b < 64; b++) {
        int j = j0 + b;
        float4 bj = sb[b];
        float aj = (bj.z - bj.x) * (bj.w - bj.y);
        float lx = fmaxf(bi.x, bj.x), ly = fmaxf(bi.y, bj.y);
        float rx = fminf(bi.z, bj.z), ry = fminf(bi.w, bj.w);
        float ww = fmaxf(rx - lx, 0.f), hh = fmaxf(ry - ly, 0.f);
        float inter = ww * hh;
        float iou = inter / (ai + aj - inter);
        if (j > i && j < PRE && iou > 0.7f) bits |= 1ULL << b;
    }
    g_mask[(size_t)i * NW + cb] = bits;
}

// ---------------------------------------------------------------- serial NMS: 1 warp, uniform live words, 16-wide lookahead
__global__ void k_nms(float* __restrict__ out) {
    __shared__ int s_keep[POST];
    int lane = threadIdx.x;        // 32 threads

    // lane owns words: lane, lane+32, lane+64  (valid words < 94)
    u64 rem0 = 0ULL, rem1 = 0ULL, rem2 = 0ULL;
    if (lane == 29) rem2 = (~0ULL) << 48;    // word 93: indices 6000..6015 invalid
    if (lane >= 30) rem2 = ~0ULL;            // words 94,95 don't exist

    int nk = 0;
    while (nk < POST) {
        // ---- free-word ballots (once per round)
        u64 f0 = ~rem0, f1 = ~rem1, f2 = ~rem2;
        unsigned b0 = __ballot_sync(FULL, f0 != 0ULL);
        unsigned b1 = __ballot_sync(FULL, f1 != 0ULL);
        unsigned b2 = __ballot_sync(FULL, f2 != 0ULL);

        // ---- pick first two free words (uniform)
        int wsel1 = -1, wsel2 = -1; u64 wfree1 = 0ULL, wfree2 = 0ULL;
        if (b0) {
            int src = __ffs(b0) - 1; wsel1 = src;
            wfree1 = __shfl_sync(FULL, f0, src);
            b0 &= b0 - 1;
        } else if (b1) {
            int src = __ffs(b1) - 1; wsel1 = src + 32;
            wfree1 = __shfl_sync(FULL, f1, src);
            b1 &= b1 - 1;
        } else if (b2) {
            int src = __ffs(b2) - 1; wsel1 = src + 64;
            wfree1 = __shfl_sync(FULL, f2, src);
            b2 &= b2 - 1;
        } else break;
        if (b0) {
            int src = __ffs(b0) - 1; wsel2 = src;
            wfree2 = __shfl_sync(FULL, f0, src);
        } else if (b1) {
            int src = __ffs(b1) - 1; wsel2 = src + 32;
            wfree2 = __shfl_sync(FULL, f1, src);
        } else if (b2) {
            int src = __ffs(b2) - 1; wsel2 = src + 64;
            wfree2 = __shfl_sync(FULL, f2, src);
        }

        // uniform live copies of the two active rem words
        u64 remw1 = ~wfree1;
        u64 remw2 = (wsel2 >= 0) ? ~wfree2 : ~0ULL;

        // ---- extract up to LOOK lowest free indices across the two words
        int j[LOOK];
        u64 t1 = wfree1, t2 = wfree2;
        #pragma unroll
        for (int m = 0; m < LOOK; m++) {
            if (t1) {
                int b = __ffsll((long long)t1) - 1;
                j[m] = (wsel1 << 6) + b;
                t1 &= t1 - 1;
            } else if (t2) {
                int b = __ffsll((long long)t2) - 1;
                j[m] = (wsel2 << 6) + b;
                t2 &= t2 - 1;
            } else j[m] = PRE;
        }

        // ---- prefetch candidate rows (triangular: clamp words < row start)
        u64 r0[LOOK], r1[LOOK], r2[LOOK];
        #pragma unroll
        for (int m = 0; m < LOOK; m++) {
            if (j[m] < PRE) {
                int sw = j[m] >> 6;
                const u64* row = g_mask + (size_t)j[m] * NW;
                r0[m] = (lane      >= sw)                   ? row[lane]      : 0ULL;
                r1[m] = (lane + 32 >= sw)                   ? row[lane + 32] : 0ULL;
                r2[m] = (lane + 64 >= sw && lane + 64 < NW) ? row[lane + 64] : 0ULL;
            } else { r0[m] = 0ULL; r1[m] = 0ULL; r2[m] = 0ULL; }
        }

        int slot1 = wsel1 >> 5, src1 = wsel1 & 31;
        int slot2 = (wsel2 >= 0) ? (wsel2 >> 5) : 0;
        int src2  = (wsel2 >= 0) ? (wsel2 & 31) : 0;

        // ---- decide candidates in ascending order (uniform control flow)
        #pragma unroll
        for (int m = 0; m < LOOK; m++) {
            int jm = j[m];
            if (jm >= PRE) break;
            int sw = jm >> 6;
            u64 bit = 1ULL << (jm & 63);
            bool inW1 = (sw == wsel1);
            if (inW1 ? (remw1 & bit) : (remw2 & bit)) continue;   // suppressed

            if (lane == 0) s_keep[nk] = jm;
            nk++;

            // broadcast row's two active words (prefetch already clamped)
            u64 val1 = (slot1 == 0) ? r0[m] : ((slot1 == 1) ? r1[m] : r2[m]);
            u64 rw1  = __shfl_sync(FULL, val1, src1);
            u64 rw2  = 0ULL;
            if (wsel2 >= 0) {
                u64 val2 = (slot2 == 0) ? r0[m] : ((slot2 == 1) ? r1[m] : r2[m]);
                rw2 = __shfl_sync(FULL, val2, src2);
            }
            remw1 |= rw1; remw2 |= rw2;
            if (inW1) remw1 |= bit; else remw2 |= bit;

            rem0 |= r0[m]; rem1 |= r1[m]; rem2 |= r2[m];
            if (lane == (sw & 31)) {
                if (sw < 32)      rem0 |= bit;
                else if (sw < 64) rem1 |= bit;
                else              rem2 |= bit;
            }
            if (nk == POST) break;
        }
    }

    __syncwarp();
    for (int k = nk + lane; k < POST; k += 32) s_keep[k] = 0;
    __syncwarp();
    for (int k = lane; k < POST; k += 32) {
        float4 b = g_top[s_keep[k]];
        out[k * 5 + 0] = 0.f;
        out[k * 5 + 1] = b.x;
        out[k * 5 + 2] = b.y;
        out[k * 5 + 3] = b.z;
        out[k * 5 + 4] = b.w;
    }
}

// ---------------------------------------------------------------- launch
extern "C" void kernel_launch(void* const* d_in, const int* in_sizes, int n_in,
                              void* d_out, int out_size) {
    const float* cls  = (const float*)d_in[0];
    const float* bbox = (const float*)d_in[1];
    const int*   ih   = (const int*)d_in[2];
    const int*   iw   = (const int*)d_in[3];
    float* out = (float*)d_out;

    k_decode <<<(NA + 255) / 256, 256>>>(cls, bbox, ih, iw);
    k_thresh <<<1, 1024>>>();
    k_compact<<<(NA + 255) / 256, 256>>>();
    k_rank2d <<<dim3(CAP / 256, CAP / 256), 256>>>();
    k_scatter<<<CAP / 256, 256>>>();
    k_mask   <<<dim3(NW, NW), 64>>>();
    k_nms    <<<1, 32>>>(out);
}